// round 4
// baseline (speedup 1.0000x reference)
#include <cuda_runtime.h>
#include <cuda_bf16.h>

#define DIM 256
#define NPAIRS 32640          // C(256,2)
#define ROWS 8                // batch rows per block
#define NTHREADS 256

// Dense coefficient matrix: M[i*DIM+j] = (w0+w1)*w0*w1 for pair k=(i,j), i<j; 0 elsewhere.
__device__ float g_M[DIM * DIM];

// perm_mat in the reference is itertools.combinations(range(256), 2) — lexicographic —
// so the pair index is closed-form:  k(i,j) = i*(DIM-1) - i*(i-1)/2 + (j-i-1),  i<j.
__global__ void genM_kernel(const float* __restrict__ w) {
    const int i = blockIdx.x;      // row     0..255
    const int j = threadIdx.x;     // column  0..255
    float v = 0.0f;
    if (i < j) {
        int k = i * (DIM - 1) - (i * (i - 1)) / 2 + (j - i - 1);
        float w0 = __ldg(&w[k]);
        float w1 = __ldg(&w[NPAIRS + k]);
        v = (w0 + w1) * w0 * w1;
    }
    g_M[i * DIM + j] = v;
}

__device__ __forceinline__ unsigned long long splat2(float m) {
    unsigned long long d;
    unsigned int r = __float_as_uint(m);
    asm("mov.b64 %0, {%1, %1};" : "=l"(d) : "r"(r));
    return d;
}

__device__ __forceinline__ void ffma2(unsigned long long& acc,
                                      unsigned long long a,
                                      unsigned long long b) {
    asm("fma.rn.f32x2 %0, %1, %2, %0;" : "+l"(acc) : "l"(a), "l"(b));
}

__device__ __forceinline__ void unpack2(unsigned long long p, float& lo, float& hi) {
    unsigned int l, h;
    asm("mov.b64 {%0, %1}, %2;" : "=r"(l), "=r"(h) : "l"(p));
    lo = __uint_as_float(l);
    hi = __uint_as_float(h);
}

// out[r] = x_r^T M x_r for ROWS rows per block.
// Thread tid owns column j = tid: acc[r] = sum_i M[i][tid] * x[r][i];
// contrib[r] = acc[r] * x[r][tid]; block-reduce contrib.
__global__ __launch_bounds__(NTHREADS) void quad_kernel(
    const float* __restrict__ x, float* __restrict__ out, int B)
{
    __shared__ float xsT[DIM][ROWS];   // transposed: xsT[col][row]
    __shared__ float red[NTHREADS / 32][ROWS];

    const int tid  = threadIdx.x;
    const int row0 = blockIdx.x * ROWS;

    // Load ROWS rows of x, transposed into smem (coalesced gmem reads).
    for (int idx = tid; idx < ROWS * DIM; idx += NTHREADS) {
        int r = idx >> 8;        // idx / DIM
        int c = idx & (DIM - 1); // idx % DIM
        float v = 0.0f;
        if (row0 + r < B) v = x[(row0 + r) * DIM + c];
        xsT[c][r] = v;
    }
    __syncthreads();

    unsigned long long acc01 = 0ull, acc23 = 0ull, acc45 = 0ull, acc67 = 0ull;

#pragma unroll 8
    for (int i = 0; i < DIM; i++) {
        float m = __ldg(&g_M[i * DIM + tid]);                          // read-only, coalesced, L2-hit
        unsigned long long mm = splat2(m);
        // rows 0-3 / 4-7 of xsT[i][]: one broadcast LDS.128 each,
        // register pairs already laid out for f32x2.
        ulonglong2 xa = *reinterpret_cast<const ulonglong2*>(&xsT[i][0]);
        ulonglong2 xb = *reinterpret_cast<const ulonglong2*>(&xsT[i][4]);
        ffma2(acc01, mm, xa.x);
        ffma2(acc23, mm, xa.y);
        ffma2(acc45, mm, xb.x);
        ffma2(acc67, mm, xb.y);
    }

    float a[ROWS];
    unpack2(acc01, a[0], a[1]);
    unpack2(acc23, a[2], a[3]);
    unpack2(acc45, a[4], a[5]);
    unpack2(acc67, a[6], a[7]);

    // Multiply by this thread's own column value x[r][tid]
    float contrib[ROWS];
    {
        float4 xc = *reinterpret_cast<const float4*>(&xsT[tid][0]);
        float4 xd = *reinterpret_cast<const float4*>(&xsT[tid][4]);
        contrib[0] = a[0] * xc.x;  contrib[1] = a[1] * xc.y;
        contrib[2] = a[2] * xc.z;  contrib[3] = a[3] * xc.w;
        contrib[4] = a[4] * xd.x;  contrib[5] = a[5] * xd.y;
        contrib[6] = a[6] * xd.z;  contrib[7] = a[7] * xd.w;
    }

    // Warp reduction
#pragma unroll
    for (int off = 16; off > 0; off >>= 1) {
#pragma unroll
        for (int r = 0; r < ROWS; r++)
            contrib[r] += __shfl_down_sync(0xffffffffu, contrib[r], off);
    }
    const int lane = tid & 31;
    const int warp = tid >> 5;
    if (lane == 0) {
#pragma unroll
        for (int r = 0; r < ROWS; r++) red[warp][r] = contrib[r];
    }
    __syncthreads();

    // Final cross-warp reduce: threads 0..ROWS-1 each own one output row.
    if (tid < ROWS) {
        float s = 0.0f;
#pragma unroll
        for (int w = 0; w < NTHREADS / 32; w++) s += red[w][tid];
        if (row0 + tid < B) out[row0 + tid] = s;
    }
}

extern "C" void kernel_launch(void* const* d_in, const int* in_sizes, int n_in,
                              void* d_out, int out_size) {
    const float* x = (const float*)d_in[0];   // [B, 256] float32
    const float* w = (const float*)d_in[1];   // [1, 2, 32640] float32
    // d_in[2] (perm_mat) is lexicographic C(256,2) — recomputed in closed form.
    float* out = (float*)d_out;               // [B, 1] float32

    const int B = in_sizes[0] / DIM;

    genM_kernel<<<DIM, DIM>>>(w);

    const int nblk = (B + ROWS - 1) / ROWS;
    quad_kernel<<<nblk, NTHREADS>>>(x, out, B);
}